// round 15
// baseline (speedup 1.0000x reference)
#include <cuda_runtime.h>
#include <cuda_fp16.h>
#include <cstddef>

// ---------------- problem constants ----------------
#define BATCH   8
#define EMEM    2
#define BE      16
#define NTOK    512
#define ROWS    (BE*NTOK)   // 8192
#define DIM     768
#define NHEADS  12
#define HDIM    64
#define LAYERS  8
#define DMLP    3072
#define QKVD    2304
#define VIEWS   2

// ---------------- scratch ----------------
__device__ float g_x[ROWS*DIM];
__device__ int   g_vismode;
__device__ unsigned g_qkvp[ROWS*(QKVD/2)];
__device__ unsigned g_a[ROWS*(DIM/2)];
__device__ unsigned g_m[ROWS*(DMLP/2)];
__device__ unsigned g_z2[ROWS*(DIM/2)];
__device__ unsigned g_wqkv[LAYERS*(DIM/2)*QKVD];
__device__ unsigned g_wo  [LAYERS*(DIM/2)*DIM];
__device__ unsigned g_w1  [LAYERS*(DIM/2)*DMLP];
__device__ unsigned g_w2  [LAYERS*(DMLP/2)*DIM];
__device__ unsigned g_nw  [(DIM/2)*DIM];

// ---------------- helpers ----------------
__device__ __forceinline__ float gelu_f(float x) {
    float x3 = x*x*x;
    return 0.5f*x*(1.f + tanhf(0.79788456080286535588f*(x + 0.044715f*x3)));
}

__device__ __forceinline__ unsigned packh2(float x, float y) {
    __half2 h = __floats2half2_rn(x, y);
    return *reinterpret_cast<unsigned*>(&h);
}

__device__ __forceinline__ void mma_f16(float& c0, float& c1, float& c2, float& c3,
                                        unsigned a0, unsigned a1, unsigned a2, unsigned a3,
                                        unsigned b0, unsigned b1)
{
    asm volatile(
        "mma.sync.aligned.m16n8k16.row.col.f32.f16.f16.f32 "
        "{%0,%1,%2,%3},{%4,%5,%6,%7},{%8,%9},{%0,%1,%2,%3};"
        : "+f"(c0), "+f"(c1), "+f"(c2), "+f"(c3)
        : "r"(a0), "r"(a1), "r"(a2), "r"(a3), "r"(b0), "r"(b1));
}

// ---------------- probe dtype of `visible` ----------------
__global__ void probe_visible(const unsigned char* __restrict__ vis) {
    if (threadIdx.x == 0 && blockIdx.x == 0) {
        int nz1 = 0, nz3f = 0;
        for (int i = 0; i < 4096; i++) {
            int m = i & 3;
            if (m == 1 && vis[i]) nz1++;
            if (m == 3 && vis[i]) nz3f++;
        }
        if (nz1 != 0)       g_vismode = 0;
        else if (nz3f != 0) g_vismode = 2;
        else                g_vismode = 1;
    }
}

// ---------------- weight/activation rounding (vectorized) ----------------
__global__ void round_W4(const float* __restrict__ W, unsigned* __restrict__ o,
                         int N, long total4)
{
    long i4 = (long)blockIdx.x*256 + threadIdx.x;
    if (i4 >= total4) return;
    int n4 = N >> 2;
    long kp = i4 / n4;
    int nq = (int)(i4 % n4) * 4;
    float4 a = *(const float4*)&W[(size_t)(2*kp)*N + nq];
    float4 b = *(const float4*)&W[(size_t)(2*kp+1)*N + nq];
    uint4 r;
    r.x = packh2(a.x, b.x);
    r.y = packh2(a.y, b.y);
    r.z = packh2(a.z, b.z);
    r.w = packh2(a.w, b.w);
    *(uint4*)&o[kp*N + nq] = r;
}

__global__ void round_A4(const float* __restrict__ X, unsigned* __restrict__ o, long total4)
{
    long i4 = (long)blockIdx.x*256 + threadIdx.x;
    if (i4 >= total4) return;
    float4 v0 = *(const float4*)&X[8*i4];
    float4 v1 = *(const float4*)&X[8*i4 + 4];
    uint4 r;
    r.x = packh2(v0.x, v0.y);
    r.y = packh2(v0.z, v0.w);
    r.z = packh2(v1.x, v1.y);
    r.w = packh2(v1.z, v1.w);
    *(uint4*)&o[4*i4] = r;
}

// ---------------- patch embed + mask + pos + noise bias ----------------
__global__ void embed_kernel(const float* __restrict__ fields,
                             const unsigned char* __restrict__ visible,
                             const float* __restrict__ W_in,
                             const float* __restrict__ mask_emb,
                             const float* __restrict__ pos_emb,
                             const float* __restrict__ noise_b,
                             float* __restrict__ xout)
{
    int row = blockIdx.x;
    int be  = row >> 9;
    int n   = row & 511;
    int b   = be >> 1;
    int h   = n >> 5;
    int w   = n & 31;

    int vi = b*NTOK + n;
    bool vis;
    int mode = g_vismode;
    if (mode == 1)      vis = ((const int*)visible)[vi] != 0;
    else if (mode == 2) vis = ((const float*)visible)[vi] != 0.f;
    else                vis = visible[vi] != 0;

    __shared__ float fv[32];
    if (threadIdx.x < 32) {
        int v = threadIdx.x >> 4;
        int p = (threadIdx.x >> 2) & 3;
        int q = threadIdx.x & 3;
        fv[threadIdx.x] = fields[((size_t)(b*VIEWS + v)*64 + (h*4+p))*128 + (w*4+q)];
    }
    __syncthreads();

    for (int d = threadIdx.x; d < DIM; d += blockDim.x) {
        float acc;
        if (vis) {
            acc = 0.f;
            #pragma unroll
            for (int t = 0; t < 32; t++) acc += fv[t] * W_in[t*DIM + d];
        } else {
            acc = mask_emb[d];
        }
        xout[(size_t)row*DIM + d] = acc + pos_emb[n*DIM + d] + noise_b[d];
    }
}

// ---------------- fp16 GEMM: 128x128 tiles, 256 threads (small-grid GEMMs) ----------------
#define GH_SMEM ((3*128*20 + 3*16*136)*4)   // 56832 B
__global__ void __launch_bounds__(256) gemm_h(
    const unsigned* __restrict__ Apk, int ldap,
    const unsigned* __restrict__ Wp, int ldb,
    float* __restrict__ Cf, unsigned* __restrict__ Cp, int ldc,
    int K, const float* __restrict__ bias, int flags)
{
    extern __shared__ unsigned sm[];
    unsigned* As = sm;
    unsigned* Bs = As + 3*128*20;

    const int tid = threadIdx.x, lane = tid & 31, wid = tid >> 5;
    const int warpM = (wid >> 2)*64, warpN = (wid & 3)*32;
    const int gid = lane >> 2, tig = lane & 3;
    const int row0 = blockIdx.y*128, col0 = blockIdx.x*128;
    const int kt32 = K >> 5;

    float acc[4][4][4] = {};

    auto issue = [&](int kt) {
        int st = kt % 3;
        int kp0 = kt << 4;
        #pragma unroll
        for (int i = 0; i < 2; i++) {
            int c = tid + i*256;
            int r = c >> 2, q = (c & 3)*4;
            const unsigned* s = &Apk[(size_t)(row0+r)*ldap + kp0 + q];
            unsigned d = (unsigned)__cvta_generic_to_shared(&As[st*2560 + r*20 + q]);
            asm volatile("cp.async.cg.shared.global [%0],[%1],16;"::"r"(d),"l"(s));
            int kp = c >> 5, nq = (c & 31)*4;
            const unsigned* s1 = &Wp[(size_t)(kp0+kp)*ldb + col0 + nq];
            unsigned d1 = (unsigned)__cvta_generic_to_shared(&Bs[st*2176 + kp*136 + nq]);
            asm volatile("cp.async.cg.shared.global [%0],[%1],16;"::"r"(d1),"l"(s1));
        }
        asm volatile("cp.async.commit_group;");
    };

    issue(0); issue(1);

    for (int kt = 0; kt < kt32; kt++) {
        int st = kt % 3;
        asm volatile("cp.async.wait_group 1;");
        __syncthreads();
        if (kt + 2 < kt32) issue(kt + 2);
        else asm volatile("cp.async.commit_group;");

        #pragma unroll
        for (int t = 0; t < 2; t++) {
            unsigned a[4][4];
            #pragma unroll
            for (int mi = 0; mi < 4; mi++) {
                int base = st*2560 + (warpM + mi*16 + gid)*20 + t*8;
                a[mi][0] = As[base + tig];
                a[mi][1] = As[base + 160 + tig];
                a[mi][2] = As[base + tig + 4];
                a[mi][3] = As[base + 160 + tig + 4];
            }
            #pragma unroll
            for (int ni = 0; ni < 4; ni++) {
                int cb = warpN + ni*8 + gid;
                unsigned b0 = Bs[st*2176 + (t*8+tig  )*136 + cb];
                unsigned b1 = Bs[st*2176 + (t*8+tig+4)*136 + cb];
                #pragma unroll
                for (int mi = 0; mi < 4; mi++) {
                    mma_f16(acc[mi][ni][0], acc[mi][ni][1], acc[mi][ni][2], acc[mi][ni][3],
                            a[mi][0], a[mi][1], a[mi][2], a[mi][3], b0, b1);
                }
            }
        }
    }

    #pragma unroll
    for (int mi = 0; mi < 4; mi++) {
        #pragma unroll
        for (int ni = 0; ni < 4; ni++) {
            int col = col0 + warpN + ni*8 + tig*2;
            float bia0 = bias ? bias[col]   : 0.f;
            float bia1 = bias ? bias[col+1] : 0.f;
            #pragma unroll
            for (int half = 0; half < 2; half++) {
                int row = row0 + warpM + mi*16 + gid + half*8;
                float v0 = acc[mi][ni][half*2 + 0] + bia0;
                float v1 = acc[mi][ni][half*2 + 1] + bia1;
                if (flags & 1) { v0 = gelu_f(v0); v1 = gelu_f(v1); }
                if (flags & 4) {
                    Cp[(size_t)row*(ldc >> 1) + (col >> 1)] = packh2(v0, v1);
                } else {
                    size_t ci = (size_t)row*ldc + col;
                    if (flags & 2) { v0 += Cf[ci]; v1 += Cf[ci+1]; }
                    Cf[ci]   = v0;
                    Cf[ci+1] = v1;
                }
            }
        }
    }
}

// ---------------- fp16 GEMM: 256x128 tiles, 512 threads (large-grid GEMMs) ----------------
// Halves B-panel re-reads vs 128-row tiles; A traffic and k-order unchanged.
#define GH2_SMEM ((3*256*20 + 3*16*136)*4)   // 87552 B
__global__ void __launch_bounds__(512) gemm_h2(
    const unsigned* __restrict__ Apk, int ldap,
    const unsigned* __restrict__ Wp, int ldb,
    float* __restrict__ Cf, unsigned* __restrict__ Cp, int ldc,
    int K, const float* __restrict__ bias, int flags)
{
    extern __shared__ unsigned sm[];
    unsigned* As = sm;                 // [3][256][20]
    unsigned* Bs = As + 3*256*20;      // [3][16][136]

    const int tid = threadIdx.x, lane = tid & 31, wid = tid >> 5;   // wid 0..15
    const int warpM = (wid >> 2)*64, warpN = (wid & 3)*32;
    const int gid = lane >> 2, tig = lane & 3;
    const int row0 = blockIdx.y*256, col0 = blockIdx.x*128;
    const int kt32 = K >> 5;

    float acc[4][4][4] = {};

    auto issue = [&](int kt) {
        int st = kt % 3;
        int kp0 = kt << 4;
        #pragma unroll
        for (int i = 0; i < 2; i++) {   // A: 256x16 = 4096 u32 = 1024 uint4
            int c = tid + i*512;
            int r = c >> 2, q = (c & 3)*4;
            const unsigned* s = &Apk[(size_t)(row0+r)*ldap + kp0 + q];
            unsigned d = (unsigned)__cvta_generic_to_shared(&As[st*5120 + r*20 + q]);
            asm volatile("cp.async.cg.shared.global [%0],[%1],16;"::"r"(d),"l"(s));
        }
        {   // B: 16x128 = 2048 u32 = 512 uint4
            int kp = tid >> 5, nq = (tid & 31)*4;
            const unsigned* s1 = &Wp[(size_t)(kp0+kp)*ldb + col0 + nq];
            unsigned d1 = (unsigned)__cvta_generic_to_shared(&Bs[st*2176 + kp*136 + nq]);
            asm volatile("cp.async.cg.shared.global [%0],[%1],16;"::"r"(d1),"l"(s1));
        }
        asm volatile("cp.async.commit_group;");
    };

    issue(0); issue(1);

    for (int kt = 0; kt < kt32; kt++) {
        int st = kt % 3;
        asm volatile("cp.async.wait_group 1;");
        __syncthreads();
        if (kt + 2 < kt32) issue(kt + 2);
        else asm volatile("cp.async.commit_group;");

        #pragma unroll
        for (int t = 0; t < 2; t++) {
            unsigned a[4][4];
            #pragma unroll
            for (int mi = 0; mi < 4; mi++) {
                int base = st*5120 + (warpM + mi*16 + gid)*20 + t*8;
                a[mi][0] = As[base + tig];
                a[mi][1] = As[base + 160 + tig];
                a[mi][2] = As[base + tig + 4];
                a[mi][3] = As[base + 160 + tig + 4];
            }
            #pragma unroll
            for (int ni = 0; ni < 4; ni++) {
                int cb = warpN + ni*8 + gid;
                unsigned b0 = Bs[st*2176 + (t*8+tig  )*136 + cb];
                unsigned b1 = Bs[st*2176 + (t*8+tig+4)*136 + cb];
                #pragma unroll
                for (int mi = 0; mi < 4; mi++) {
                    mma_f16(acc[mi][ni][0], acc[mi][ni][1], acc[mi][ni][2], acc[mi][ni][3],
                            a[mi][0], a[mi][1], a[mi][2], a[mi][3], b0, b1);
                }
            }
        }
    }

    #pragma unroll
    for (int mi = 0; mi < 4; mi++) {
        #pragma unroll
        for (int ni = 0; ni < 4; ni++) {
            int col = col0 + warpN + ni*8 + tig*2;
            float bia0 = bias ? bias[col]   : 0.f;
            float bia1 = bias ? bias[col+1] : 0.f;
            #pragma unroll
            for (int half = 0; half < 2; half++) {
                int row = row0 + warpM + mi*16 + gid + half*8;
                float v0 = acc[mi][ni][half*2 + 0] + bia0;
                float v1 = acc[mi][ni][half*2 + 1] + bia1;
                if (flags & 1) { v0 = gelu_f(v0); v1 = gelu_f(v1); }
                if (flags & 4) {
                    Cp[(size_t)row*(ldc >> 1) + (col >> 1)] = packh2(v0, v1);
                } else {
                    size_t ci = (size_t)row*ldc + col;
                    if (flags & 2) { v0 += Cf[ci]; v1 += Cf[ci+1]; }
                    Cf[ci]   = v0;
                    Cf[ci+1] = v1;
                }
            }
        }
    }
}

// ---------------- flash attention: single pass, register S, online softmax ----------------
__global__ void __launch_bounds__(256) attn_flash(const unsigned* __restrict__ qkvp,
                                                  unsigned* __restrict__ Ha)
{
    __shared__ unsigned Kb[2][64*36];
    __shared__ unsigned Vr[2][64*36];
    __shared__ unsigned Vp[32*72];

    const int bh = blockIdx.y;
    const int qt = blockIdx.x * 128;
    const int be = bh / NHEADS, nh = bh % NHEADS;
    const unsigned* Qg = qkvp + (size_t)be*NTOK*1152 + nh*32;
    const unsigned* Kg = Qg + 384;
    const unsigned* Vg = Qg + 768;

    const int tid = threadIdx.x, lane = tid & 31, wid = tid >> 5;
    const int gid = lane >> 2, tig = lane & 3;

    auto pref = [&](int kt) {
        int buf = kt & 1;
        #pragma unroll
        for (int i = 0; i < 2; i++) {
            int c = tid + i*256;
            int r = c >> 3, q = (c & 7)*4;
            unsigned dk = (unsigned)__cvta_generic_to_shared(&Kb[buf][r*36 + q]);
            const unsigned* sk = &Kg[(size_t)(kt*64+r)*1152 + q];
            asm volatile("cp.async.cg.shared.global [%0],[%1],16;"::"r"(dk),"l"(sk));
            unsigned dv = (unsigned)__cvta_generic_to_shared(&Vr[buf][r*36 + q]);
            const unsigned* sv = &Vg[(size_t)(kt*64+r)*1152 + q];
            asm volatile("cp.async.cg.shared.global [%0],[%1],16;"::"r"(dv),"l"(sv));
        }
        asm volatile("cp.async.commit_group;");
    };

    pref(0); pref(1);

    unsigned qf[4][4];
    {
        const unsigned* Qrow = &Qg[(size_t)(qt + wid*16)*1152];
        __half2 s8 = __half2half2(__float2half(0.125f));
        #pragma unroll
        for (int t = 0; t < 4; t++) {
            qf[t][0] = Qrow[(size_t)(gid  )*1152 + t*8 + tig];
            qf[t][1] = Qrow[(size_t)(gid+8)*1152 + t*8 + tig];
            qf[t][2] = Qrow[(size_t)(gid  )*1152 + t*8 + tig+4];
            qf[t][3] = Qrow[(size_t)(gid+8)*1152 + t*8 + tig+4];
            #pragma unroll
            for (int j = 0; j < 4; j++) {
                __half2 h = __hmul2(*reinterpret_cast<__half2*>(&qf[t][j]), s8);
                qf[t][j] = *reinterpret_cast<unsigned*>(&h);
            }
        }
    }

    float m0 = -1e30f, m1 = -1e30f, l0 = 0.f, l1 = 0.f;
    float acc[8][4] = {};

    for (int kt = 0; kt < 8; kt++) {
        const int buf = kt & 1;
        asm volatile("cp.async.wait_group 1;");
        __syncthreads();

        float s[8][4] = {};
        #pragma unroll
        for (int t = 0; t < 4; t++) {
            #pragma unroll
            for (int ni = 0; ni < 8; ni++) {
                int cb = ni*8 + gid;
                unsigned b0 = Kb[buf][cb*36 + t*8 + tig];
                unsigned b1 = Kb[buf][cb*36 + t*8 + tig+4];
                mma_f16(s[ni][0], s[ni][1], s[ni][2], s[ni][3],
                        qf[t][0], qf[t][1], qf[t][2], qf[t][3], b0, b1);
            }
        }

        float tm0 = -1e30f, tm1 = -1e30f;
        #pragma unroll
        for (int ni = 0; ni < 8; ni++) {
            tm0 = fmaxf(tm0, fmaxf(s[ni][0], s[ni][1]));
            tm1 = fmaxf(tm1, fmaxf(s[ni][2], s[ni][3]));
        }
        tm0 = fmaxf(tm0, __shfl_xor_sync(0xffffffffu, tm0, 1));
        tm0 = fmaxf(tm0, __shfl_xor_sync(0xffffffffu, tm0, 2));
        tm1 = fmaxf(tm1, __shfl_xor_sync(0xffffffffu, tm1, 1));
        tm1 = fmaxf(tm1, __shfl_xor_sync(0xffffffffu, tm1, 2));
        float nm0 = fmaxf(m0, tm0), nm1 = fmaxf(m1, tm1);
        float f0 = __expf(m0 - nm0), f1 = __expf(m1 - nm1);
        m0 = nm0; m1 = nm1;

        unsigned pp[8][2];
        float ts0 = 0.f, ts1 = 0.f;
        #pragma unroll
        for (int ni = 0; ni < 8; ni++) {
            float p0 = __expf(s[ni][0] - m0), p1 = __expf(s[ni][1] - m0);
            float p2 = __expf(s[ni][2] - m1), p3 = __expf(s[ni][3] - m1);
            ts0 += p0 + p1; ts1 += p2 + p3;
            pp[ni][0] = packh2(p0, p1);
            pp[ni][1] = packh2(p2, p3);
        }
        ts0 += __shfl_xor_sync(0xffffffffu, ts0, 1);
        ts0 += __shfl_xor_sync(0xffffffffu, ts0, 2);
        ts1 += __shfl_xor_sync(0xffffffffu, ts1, 1);
        ts1 += __shfl_xor_sync(0xffffffffu, ts1, 2);
        l0 = l0*f0 + ts0;
        l1 = l1*f1 + ts1;
        #pragma unroll
        for (int ni = 0; ni < 8; ni++) {
            acc[ni][0] *= f0; acc[ni][1] *= f0;
            acc[ni][2] *= f1; acc[ni][3] *= f1;
        }

        {
            int kp = tid >> 3, dpb = tid & 7;
            #pragma unroll
            for (int i = 0; i < 4; i++) {
                int dp = dpb + 8*i;
                unsigned r0 = Vr[buf][(2*kp  )*36 + dp];
                unsigned r1 = Vr[buf][(2*kp+1)*36 + dp];
                Vp[kp*72 + 2*dp    ] = __byte_perm(r0, r1, 0x5410);
                Vp[kp*72 + 2*dp + 1] = __byte_perm(r0, r1, 0x7632);
            }
        }
        __syncthreads();
        if (kt + 2 < 8) pref(kt + 2);
        else asm volatile("cp.async.commit_group;");

        #pragma unroll
        for (int b = 0; b < 4; b++) {
            unsigned a0 = pp[2*b  ][0], a1 = pp[2*b  ][1];
            unsigned a2 = pp[2*b+1][0], a3 = pp[2*b+1][1];
            #pragma unroll
            for (int ni = 0; ni < 8; ni++) {
                int cb = ni*8 + gid;
                unsigned b0 = Vp[(b*8 + tig  )*72 + cb];
                unsigned b1 = Vp[(b*8 + tig+4)*72 + cb];
                mma_f16(acc[ni][0], acc[ni][1], acc[ni][2], acc[ni][3],
                        a0, a1, a2, a3, b0, b1);
            }
        }
    }

    float il0 = 1.f / l0, il1 = 1.f / l1;
    int row0 = be*NTOK + qt + wid*16 + gid;
    #pragma unroll
    for (int ni = 0; ni < 8; ni++) {
        int colp = nh*32 + ni*4 + tig;
        Ha[(size_t)row0*384 + colp]     = packh2(acc[ni][0]*il0, acc[ni][1]*il0);
        Ha[(size_t)(row0+8)*384 + colp] = packh2(acc[ni][2]*il1, acc[ni][3]*il1);
    }
}

// ---------------- layernorm: warp per row ----------------
__global__ void __launch_bounds__(256) ln_h(const float* __restrict__ x,
                                            const float* __restrict__ s,
                                            const float* __restrict__ b,
                                            unsigned* __restrict__ ho)
{
    const int lane = threadIdx.x & 31, wid = threadIdx.x >> 5;
    const int row = blockIdx.x*8 + wid;
    const float* xr = x + (size_t)row*DIM;

    float4 v[6];
    float sum = 0.f;
    #pragma unroll
    for (int i = 0; i < 6; i++) {
        v[i] = *(const float4*)&xr[(lane + 32*i)*4];
        sum += v[i].x + v[i].y + v[i].z + v[i].w;
    }
    #pragma unroll
    for (int off = 16; off > 0; off >>= 1)
        sum += __shfl_xor_sync(0xffffffffu, sum, off);
    float mu = sum * (1.f/768.f);

    float sq = 0.f;
    #pragma unroll
    for (int i = 0; i < 6; i++) {
        v[i].x -= mu; v[i].y -= mu; v[i].z -= mu; v[i].w -= mu;
        sq += v[i].x*v[i].x + v[i].y*v[i].y + v[i].z*v[i].z + v[i].w*v[i].w;
    }
    #pragma unroll
    for (int off = 16; off > 0; off >>= 1)
        sq += __shfl_xor_sync(0xffffffffu, sq, off);
    float rstd = rsqrtf(sq*(1.f/768.f) + 1e-5f);

    #pragma unroll
    for (int i = 0; i < 6; i++) {
        int e = (lane + 32*i)*4;
        float4 sv = *(const float4*)&s[e];
        float4 bv = *(const float4*)&b[e];
        float y0 = v[i].x*rstd*sv.x + bv.x;
        float y1 = v[i].y*rstd*sv.y + bv.y;
        float y2 = v[i].z*rstd*sv.z + bv.z;
        float y3 = v[i].w*rstd*sv.w + bv.w;
        *(uint2*)&ho[(size_t)row*384 + (lane + 32*i)*2] =
            make_uint2(packh2(y0, y1), packh2(y2, y3));
    }
}

// ---------------- unpatchify ----------------
__global__ void __launch_bounds__(256) out_kernel(const float* __restrict__ x,
                                                  const float* __restrict__ W_out,
                                                  float* __restrict__ out)
{
    __shared__ float srow[8*768];
    const int tid = threadIdx.x, lane = tid & 31, wid = tid >> 5;
    const int rowbase = blockIdx.x*8;

    #pragma unroll
    for (int i = 0; i < 6; i++) {
        int f = tid + i*256;
        int r = f / 192, pos = f % 192;
        *(float4*)&srow[r*768 + pos*4] =
            *(const float4*)&x[(size_t)(rowbase+r)*DIM + pos*4];
    }
    __syncthreads();

    const int row = rowbase + wid;
    const int v  = lane >> 4;
    const int pq = lane & 15;
    const float* xrow = &srow[wid*768];
    const float* wcol = W_out + (size_t)v*DIM*16 + pq;

    float acc = 0.f;
    #pragma unroll 8
    for (int d = 0; d < DIM; d++)
        acc = fmaf(xrow[d], wcol[(size_t)d*16], acc);

    int bb = row >> 10;
    int e  = (row >> 9) & 1;
    int n  = row & 511;
    int h  = n >> 5, w = n & 31;
    int p  = pq >> 2, q = pq & 3;
    size_t oidx = (size_t)bb*32768 + (size_t)v*16384
                + (size_t)(h*4+p)*256 + (w*4+q)*2 + e;
    out[oidx] = acc;
}

// ---------------- driver ----------------
extern "C" void kernel_launch(void* const* d_in, const int* in_sizes, int n_in,
                              void* d_out, int out_size)
{
    const float* fields   = (const float*)d_in[0];
    const unsigned char* visible = (const unsigned char*)d_in[1];
    const float* z        = (const float*)d_in[2];
    const float* W_in     = (const float*)d_in[3];
    const float* W_out    = (const float*)d_in[4];
    const float* noise_W  = (const float*)d_in[5];
    const float* noise_b  = (const float*)d_in[6];
    const float* mask_emb = (const float*)d_in[7];
    const float* pos_emb  = (const float*)d_in[8];
    const float* ln1_s    = (const float*)d_in[9];
    const float* ln1_b    = (const float*)d_in[10];
    const float* Wqkv     = (const float*)d_in[11];
    const float* bqkv     = (const float*)d_in[12];
    const float* Wo       = (const float*)d_in[13];
    const float* bo       = (const float*)d_in[14];
    const float* ln2_s    = (const float*)d_in[15];
    const float* ln2_b    = (const float*)d_in[16];
    const float* W1       = (const float*)d_in[17];
    const float* b1       = (const float*)d_in[18];
    const float* W2       = (const float*)d_in[19];
    const float* b2       = (const float*)d_in[20];

    float *xp;
    unsigned *qkvpp, *ap, *mp, *zp;
    unsigned *wq, *wo, *w1, *w2, *nw;
    cudaGetSymbolAddress((void**)&xp,    g_x);
    cudaGetSymbolAddress((void**)&qkvpp, g_qkvp);
    cudaGetSymbolAddress((void**)&ap,    g_a);
    cudaGetSymbolAddress((void**)&mp,    g_m);
    cudaGetSymbolAddress((void**)&zp,    g_z2);
    cudaGetSymbolAddress((void**)&wq,    g_wqkv);
    cudaGetSymbolAddress((void**)&wo,    g_wo);
    cudaGetSymbolAddress((void**)&w1,    g_w1);
    cudaGetSymbolAddress((void**)&w2,    g_w2);
    cudaGetSymbolAddress((void**)&nw,    g_nw);

    cudaFuncSetAttribute(gemm_h,  cudaFuncAttributeMaxDynamicSharedMemorySize, GH_SMEM);
    cudaFuncSetAttribute(gemm_h2, cudaFuncAttributeMaxDynamicSharedMemorySize, GH2_SMEM);

    probe_visible<<<1, 32>>>(visible);

    {
        long t4;
        t4 = (long)LAYERS*384*QKVD/4;
        round_W4<<<(unsigned)((t4+255)/256), 256>>>(Wqkv, wq, QKVD, t4);
        t4 = (long)LAYERS*384*DIM/4;
        round_W4<<<(unsigned)((t4+255)/256), 256>>>(Wo, wo, DIM, t4);
        t4 = (long)LAYERS*384*DMLP/4;
        round_W4<<<(unsigned)((t4+255)/256), 256>>>(W1, w1, DMLP, t4);
        t4 = (long)LAYERS*1536*DIM/4;
        round_W4<<<(unsigned)((t4+255)/256), 256>>>(W2, w2, DIM, t4);
        t4 = (long)384*DIM/4;
        round_W4<<<(unsigned)((t4+255)/256), 256>>>(noise_W, nw, DIM, t4);
        t4 = (long)ROWS*384/4;
        round_A4<<<(unsigned)((t4+255)/256), 256>>>(z, zp, t4);
    }

    embed_kernel<<<ROWS, 256>>>(fields, visible, W_in, mask_emb, pos_emb, noise_b, xp);

    // x += z @ noise_W
    gemm_h<<<dim3(DIM/128, ROWS/128), 256, GH_SMEM>>>(
        zp, 384, nw, DIM, xp, nullptr, DIM, DIM, nullptr, 2);

    for (int l = 0; l < LAYERS; l++) {
        ln_h<<<ROWS/8, 256>>>(xp, ln1_s + l*DIM, ln1_b + l*DIM, ap);

        gemm_h2<<<dim3(QKVD/128, ROWS/256), 512, GH2_SMEM>>>(
            ap, 384,
            wq + (size_t)l*384*QKVD, QKVD,
            nullptr, qkvpp, QKVD, DIM, bqkv + (size_t)l*QKVD, 4);

        attn_flash<<<dim3(NTOK/128, BE*NHEADS), 256>>>(qkvpp, ap);

        gemm_h<<<dim3(DIM/128, ROWS/128), 256, GH_SMEM>>>(
            ap, 384,
            wo + (size_t)l*384*DIM, DIM,
            xp, nullptr, DIM, DIM, bo + (size_t)l*DIM, 2);

        ln_h<<<ROWS/8, 256>>>(xp, ln2_s + l*DIM, ln2_b + l*DIM, ap);

        gemm_h2<<<dim3(DMLP/128, ROWS/256), 512, GH2_SMEM>>>(
            ap, 384,
            w1 + (size_t)l*384*DMLP, DMLP,
            nullptr, mp, DMLP, DIM, b1 + (size_t)l*DMLP, 1|4);

        gemm_h<<<dim3(DIM/128, ROWS/128), 256, GH_SMEM>>>(
            mp, 1536,
            w2 + (size_t)l*1536*DIM, DIM,
            xp, nullptr, DIM, DMLP, b2 + (size_t)l*DIM, 2);
    }

    out_kernel<<<ROWS/8, 256>>>(xp, W_out, (float*)d_out);
}

// round 16
// speedup vs baseline: 1.0574x; 1.0574x over previous
#include <cuda_runtime.h>
#include <cuda_fp16.h>
#include <cstddef>

// ---------------- problem constants ----------------
#define BATCH   8
#define EMEM    2
#define BE      16
#define NTOK    512
#define ROWS    (BE*NTOK)   // 8192
#define DIM     768
#define NHEADS  12
#define HDIM    64
#define LAYERS  8
#define DMLP    3072
#define QKVD    2304
#define VIEWS   2

// ---------------- scratch ----------------
__device__ float g_x[ROWS*DIM];
__device__ int   g_vismode;
__device__ unsigned g_qkvp[ROWS*(QKVD/2)];
__device__ unsigned g_a[ROWS*(DIM/2)];
__device__ unsigned g_m[ROWS*(DMLP/2)];
__device__ unsigned g_z2[ROWS*(DIM/2)];
__device__ unsigned g_wqkv[LAYERS*(DIM/2)*QKVD];
__device__ unsigned g_wo  [LAYERS*(DIM/2)*DIM];
__device__ unsigned g_w1  [LAYERS*(DIM/2)*DMLP];
__device__ unsigned g_w2  [LAYERS*(DMLP/2)*DIM];
__device__ unsigned g_nw  [(DIM/2)*DIM];

// ---------------- helpers ----------------
__device__ __forceinline__ float gelu_f(float x) {
    float x3 = x*x*x;
    return 0.5f*x*(1.f + tanhf(0.79788456080286535588f*(x + 0.044715f*x3)));
}

__device__ __forceinline__ unsigned packh2(float x, float y) {
    __half2 h = __floats2half2_rn(x, y);
    return *reinterpret_cast<unsigned*>(&h);
}

__device__ __forceinline__ void mma_f16(float& c0, float& c1, float& c2, float& c3,
                                        unsigned a0, unsigned a1, unsigned a2, unsigned a3,
                                        unsigned b0, unsigned b1)
{
    asm volatile(
        "mma.sync.aligned.m16n8k16.row.col.f32.f16.f16.f32 "
        "{%0,%1,%2,%3},{%4,%5,%6,%7},{%8,%9},{%0,%1,%2,%3};"
        : "+f"(c0), "+f"(c1), "+f"(c2), "+f"(c3)
        : "r"(a0), "r"(a1), "r"(a2), "r"(a3), "r"(b0), "r"(b1));
}

// ---------------- probe dtype of `visible` ----------------
__global__ void probe_visible(const unsigned char* __restrict__ vis) {
    if (threadIdx.x == 0 && blockIdx.x == 0) {
        int nz1 = 0, nz3f = 0;
        for (int i = 0; i < 4096; i++) {
            int m = i & 3;
            if (m == 1 && vis[i]) nz1++;
            if (m == 3 && vis[i]) nz3f++;
        }
        if (nz1 != 0)       g_vismode = 0;
        else if (nz3f != 0) g_vismode = 2;
        else                g_vismode = 1;
    }
}

// ---------------- weight/activation rounding (vectorized) ----------------
__global__ void round_W4(const float* __restrict__ W, unsigned* __restrict__ o,
                         int N, long total4)
{
    long i4 = (long)blockIdx.x*256 + threadIdx.x;
    if (i4 >= total4) return;
    int n4 = N >> 2;
    long kp = i4 / n4;
    int nq = (int)(i4 % n4) * 4;
    float4 a = *(const float4*)&W[(size_t)(2*kp)*N + nq];
    float4 b = *(const float4*)&W[(size_t)(2*kp+1)*N + nq];
    uint4 r;
    r.x = packh2(a.x, b.x);
    r.y = packh2(a.y, b.y);
    r.z = packh2(a.z, b.z);
    r.w = packh2(a.w, b.w);
    *(uint4*)&o[kp*N + nq] = r;
}

__global__ void round_A4(const float* __restrict__ X, unsigned* __restrict__ o, long total4)
{
    long i4 = (long)blockIdx.x*256 + threadIdx.x;
    if (i4 >= total4) return;
    float4 v0 = *(const float4*)&X[8*i4];
    float4 v1 = *(const float4*)&X[8*i4 + 4];
    uint4 r;
    r.x = packh2(v0.x, v0.y);
    r.y = packh2(v0.z, v0.w);
    r.z = packh2(v1.x, v1.y);
    r.w = packh2(v1.z, v1.w);
    *(uint4*)&o[4*i4] = r;
}

// ---------------- patch embed + mask + pos + noise bias ----------------
__global__ void embed_kernel(const float* __restrict__ fields,
                             const unsigned char* __restrict__ visible,
                             const float* __restrict__ W_in,
                             const float* __restrict__ mask_emb,
                             const float* __restrict__ pos_emb,
                             const float* __restrict__ noise_b,
                             float* __restrict__ xout)
{
    int row = blockIdx.x;
    int be  = row >> 9;
    int n   = row & 511;
    int b   = be >> 1;
    int h   = n >> 5;
    int w   = n & 31;

    int vi = b*NTOK + n;
    bool vis;
    int mode = g_vismode;
    if (mode == 1)      vis = ((const int*)visible)[vi] != 0;
    else if (mode == 2) vis = ((const float*)visible)[vi] != 0.f;
    else                vis = visible[vi] != 0;

    __shared__ float fv[32];
    if (threadIdx.x < 32) {
        int v = threadIdx.x >> 4;
        int p = (threadIdx.x >> 2) & 3;
        int q = threadIdx.x & 3;
        fv[threadIdx.x] = fields[((size_t)(b*VIEWS + v)*64 + (h*4+p))*128 + (w*4+q)];
    }
    __syncthreads();

    for (int d = threadIdx.x; d < DIM; d += blockDim.x) {
        float acc;
        if (vis) {
            acc = 0.f;
            #pragma unroll
            for (int t = 0; t < 32; t++) acc += fv[t] * W_in[t*DIM + d];
        } else {
            acc = mask_emb[d];
        }
        xout[(size_t)row*DIM + d] = acc + pos_emb[n*DIM + d] + noise_b[d];
    }
}

// ---------------- fp16 GEMM: 128x128 tiles, k32, 3-stage cp.async ----------------
// flags: bit0 gelu, bit1 accumulate fp32, bit2 write fp16-pair output
#define GH_SMEM ((3*128*20 + 3*16*136)*4)   // 56832 B
__global__ void __launch_bounds__(256) gemm_h(
    const unsigned* __restrict__ Apk, int ldap,
    const unsigned* __restrict__ Wp, int ldb,
    float* __restrict__ Cf, unsigned* __restrict__ Cp, int ldc,
    int K, const float* __restrict__ bias, int flags)
{
    extern __shared__ unsigned sm[];
    unsigned* As = sm;
    unsigned* Bs = As + 3*128*20;

    const int tid = threadIdx.x, lane = tid & 31, wid = tid >> 5;
    const int warpM = (wid >> 2)*64, warpN = (wid & 3)*32;
    const int gid = lane >> 2, tig = lane & 3;
    const int row0 = blockIdx.y*128, col0 = blockIdx.x*128;
    const int kt32 = K >> 5;

    float acc[4][4][4] = {};

    auto issue = [&](int kt) {
        int st = kt % 3;
        int kp0 = kt << 4;
        #pragma unroll
        for (int i = 0; i < 2; i++) {
            int c = tid + i*256;
            int r = c >> 2, q = (c & 3)*4;
            const unsigned* s = &Apk[(size_t)(row0+r)*ldap + kp0 + q];
            unsigned d = (unsigned)__cvta_generic_to_shared(&As[st*2560 + r*20 + q]);
            asm volatile("cp.async.cg.shared.global [%0],[%1],16;"::"r"(d),"l"(s));
            int kp = c >> 5, nq = (c & 31)*4;
            const unsigned* s1 = &Wp[(size_t)(kp0+kp)*ldb + col0 + nq];
            unsigned d1 = (unsigned)__cvta_generic_to_shared(&Bs[st*2176 + kp*136 + nq]);
            asm volatile("cp.async.cg.shared.global [%0],[%1],16;"::"r"(d1),"l"(s1));
        }
        asm volatile("cp.async.commit_group;");
    };

    issue(0); issue(1);

    for (int kt = 0; kt < kt32; kt++) {
        int st = kt % 3;
        asm volatile("cp.async.wait_group 1;");
        __syncthreads();
        if (kt + 2 < kt32) issue(kt + 2);
        else asm volatile("cp.async.commit_group;");

        #pragma unroll
        for (int t = 0; t < 2; t++) {
            unsigned a[4][4];
            #pragma unroll
            for (int mi = 0; mi < 4; mi++) {
                int base = st*2560 + (warpM + mi*16 + gid)*20 + t*8;
                a[mi][0] = As[base + tig];
                a[mi][1] = As[base + 160 + tig];
                a[mi][2] = As[base + tig + 4];
                a[mi][3] = As[base + 160 + tig + 4];
            }
            #pragma unroll
            for (int ni = 0; ni < 4; ni++) {
                int cb = warpN + ni*8 + gid;
                unsigned b0 = Bs[st*2176 + (t*8+tig  )*136 + cb];
                unsigned b1 = Bs[st*2176 + (t*8+tig+4)*136 + cb];
                #pragma unroll
                for (int mi = 0; mi < 4; mi++) {
                    mma_f16(acc[mi][ni][0], acc[mi][ni][1], acc[mi][ni][2], acc[mi][ni][3],
                            a[mi][0], a[mi][1], a[mi][2], a[mi][3], b0, b1);
                }
            }
        }
    }

    #pragma unroll
    for (int mi = 0; mi < 4; mi++) {
        #pragma unroll
        for (int ni = 0; ni < 4; ni++) {
            int col = col0 + warpN + ni*8 + tig*2;
            float bia0 = bias ? bias[col]   : 0.f;
            float bia1 = bias ? bias[col+1] : 0.f;
            #pragma unroll
            for (int half = 0; half < 2; half++) {
                int row = row0 + warpM + mi*16 + gid + half*8;
                float v0 = acc[mi][ni][half*2 + 0] + bia0;
                float v1 = acc[mi][ni][half*2 + 1] + bia1;
                if (flags & 1) { v0 = gelu_f(v0); v1 = gelu_f(v1); }
                if (flags & 4) {
                    Cp[(size_t)row*(ldc >> 1) + (col >> 1)] = packh2(v0, v1);
                } else {
                    size_t ci = (size_t)row*ldc + col;
                    if (flags & 2) { v0 += Cf[ci]; v1 += Cf[ci+1]; }
                    Cf[ci]   = v0;
                    Cf[ci+1] = v1;
                }
            }
        }
    }
}

// ---------------- flash attention: single pass, register S, online softmax ----------------
// __launch_bounds__(256, 2): cap regs at 128 to get 2 CTAs/SM (45KB smem fits x2)
__global__ void __launch_bounds__(256, 2) attn_flash(const unsigned* __restrict__ qkvp,
                                                     unsigned* __restrict__ Ha)
{
    __shared__ unsigned Kb[2][64*36];
    __shared__ unsigned Vr[2][64*36];
    __shared__ unsigned Vp[32*72];

    const int bh = blockIdx.y;
    const int qt = blockIdx.x * 128;
    const int be = bh / NHEADS, nh = bh % NHEADS;
    const unsigned* Qg = qkvp + (size_t)be*NTOK*1152 + nh*32;
    const unsigned* Kg = Qg + 384;
    const unsigned* Vg = Qg + 768;

    const int tid = threadIdx.x, lane = tid & 31, wid = tid >> 5;
    const int gid = lane >> 2, tig = lane & 3;

    auto pref = [&](int kt) {
        int buf = kt & 1;
        #pragma unroll
        for (int i = 0; i < 2; i++) {
            int c = tid + i*256;
            int r = c >> 3, q = (c & 7)*4;
            unsigned dk = (unsigned)__cvta_generic_to_shared(&Kb[buf][r*36 + q]);
            const unsigned* sk = &Kg[(size_t)(kt*64+r)*1152 + q];
            asm volatile("cp.async.cg.shared.global [%0],[%1],16;"::"r"(dk),"l"(sk));
            unsigned dv = (unsigned)__cvta_generic_to_shared(&Vr[buf][r*36 + q]);
            const unsigned* sv = &Vg[(size_t)(kt*64+r)*1152 + q];
            asm volatile("cp.async.cg.shared.global [%0],[%1],16;"::"r"(dv),"l"(sv));
        }
        asm volatile("cp.async.commit_group;");
    };

    pref(0); pref(1);

    unsigned qf[4][4];
    {
        const unsigned* Qrow = &Qg[(size_t)(qt + wid*16)*1152];
        __half2 s8 = __half2half2(__float2half(0.125f));
        #pragma unroll
        for (int t = 0; t < 4; t++) {
            qf[t][0] = Qrow[(size_t)(gid  )*1152 + t*8 + tig];
            qf[t][1] = Qrow[(size_t)(gid+8)*1152 + t*8 + tig];
            qf[t][2] = Qrow[(size_t)(gid  )*1152 + t*8 + tig+4];
            qf[t][3] = Qrow[(size_t)(gid+8)*1152 + t*8 + tig+4];
            #pragma unroll
            for (int j = 0; j < 4; j++) {
                __half2 h = __hmul2(*reinterpret_cast<__half2*>(&qf[t][j]), s8);
                qf[t][j] = *reinterpret_cast<unsigned*>(&h);
            }
        }
    }

    float m0 = -1e30f, m1 = -1e30f, l0 = 0.f, l1 = 0.f;
    float acc[8][4] = {};

    for (int kt = 0; kt < 8; kt++) {
        const int buf = kt & 1;
        asm volatile("cp.async.wait_group 1;");
        __syncthreads();

        float s[8][4] = {};
        #pragma unroll
        for (int t = 0; t < 4; t++) {
            #pragma unroll
            for (int ni = 0; ni < 8; ni++) {
                int cb = ni*8 + gid;
                unsigned b0 = Kb[buf][cb*36 + t*8 + tig];
                unsigned b1 = Kb[buf][cb*36 + t*8 + tig+4];
                mma_f16(s[ni][0], s[ni][1], s[ni][2], s[ni][3],
                        qf[t][0], qf[t][1], qf[t][2], qf[t][3], b0, b1);
            }
        }

        float tm0 = -1e30f, tm1 = -1e30f;
        #pragma unroll
        for (int ni = 0; ni < 8; ni++) {
            tm0 = fmaxf(tm0, fmaxf(s[ni][0], s[ni][1]));
            tm1 = fmaxf(tm1, fmaxf(s[ni][2], s[ni][3]));
        }
        tm0 = fmaxf(tm0, __shfl_xor_sync(0xffffffffu, tm0, 1));
        tm0 = fmaxf(tm0, __shfl_xor_sync(0xffffffffu, tm0, 2));
        tm1 = fmaxf(tm1, __shfl_xor_sync(0xffffffffu, tm1, 1));
        tm1 = fmaxf(tm1, __shfl_xor_sync(0xffffffffu, tm1, 2));
        float nm0 = fmaxf(m0, tm0), nm1 = fmaxf(m1, tm1);
        float f0 = __expf(m0 - nm0), f1 = __expf(m1 - nm1);
        m0 = nm0; m1 = nm1;

        unsigned pp[8][2];
        float ts0 = 0.f, ts1 = 0.f;
        #pragma unroll
        for (int ni = 0; ni < 8; ni++) {
            float p0 = __expf(s[ni][0] - m0), p1 = __expf(s[ni][1] - m0);
            float p2 = __expf(s[ni][2] - m1), p3 = __expf(s[ni][3] - m1);
            ts0 += p0 + p1; ts1 += p2 + p3;
            pp[ni][0] = packh2(p0, p1);
            pp[ni][1] = packh2(p2, p3);
        }
        ts0 += __shfl_xor_sync(0xffffffffu, ts0, 1);
        ts0 += __shfl_xor_sync(0xffffffffu, ts0, 2);
        ts1 += __shfl_xor_sync(0xffffffffu, ts1, 1);
        ts1 += __shfl_xor_sync(0xffffffffu, ts1, 2);
        l0 = l0*f0 + ts0;
        l1 = l1*f1 + ts1;
        #pragma unroll
        for (int ni = 0; ni < 8; ni++) {
            acc[ni][0] *= f0; acc[ni][1] *= f0;
            acc[ni][2] *= f1; acc[ni][3] *= f1;
        }

        {
            int kp = tid >> 3, dpb = tid & 7;
            #pragma unroll
            for (int i = 0; i < 4; i++) {
                int dp = dpb + 8*i;
                unsigned r0 = Vr[buf][(2*kp  )*36 + dp];
                unsigned r1 = Vr[buf][(2*kp+1)*36 + dp];
                Vp[kp*72 + 2*dp    ] = __byte_perm(r0, r1, 0x5410);
                Vp[kp*72 + 2*dp + 1] = __byte_perm(r0, r1, 0x7632);
            }
        }
        __syncthreads();
        if (kt + 2 < 8) pref(kt + 2);
        else asm volatile("cp.async.commit_group;");

        #pragma unroll
        for (int b = 0; b < 4; b++) {
            unsigned a0 = pp[2*b  ][0], a1 = pp[2*b  ][1];
            unsigned a2 = pp[2*b+1][0], a3 = pp[2*b+1][1];
            #pragma unroll
            for (int ni = 0; ni < 8; ni++) {
                int cb = ni*8 + gid;
                unsigned b0 = Vp[(b*8 + tig  )*72 + cb];
                unsigned b1 = Vp[(b*8 + tig+4)*72 + cb];
                mma_f16(acc[ni][0], acc[ni][1], acc[ni][2], acc[ni][3],
                        a0, a1, a2, a3, b0, b1);
            }
        }
    }

    float il0 = 1.f / l0, il1 = 1.f / l1;
    int row0 = be*NTOK + qt + wid*16 + gid;
    #pragma unroll
    for (int ni = 0; ni < 8; ni++) {
        int colp = nh*32 + ni*4 + tig;
        Ha[(size_t)row0*384 + colp]     = packh2(acc[ni][0]*il0, acc[ni][1]*il0);
        Ha[(size_t)(row0+8)*384 + colp] = packh2(acc[ni][2]*il1, acc[ni][3]*il1);
    }
}

// ---------------- layernorm: warp per row ----------------
__global__ void __launch_bounds__(256) ln_h(const float* __restrict__ x,
                                            const float* __restrict__ s,
                                            const float* __restrict__ b,
                                            unsigned* __restrict__ ho)
{
    const int lane = threadIdx.x & 31, wid = threadIdx.x >> 5;
    const int row = blockIdx.x*8 + wid;
    const float* xr = x + (size_t)row*DIM;

    float4 v[6];
    float sum = 0.f;
    #pragma unroll
    for (int i = 0; i < 6; i++) {
        v[i] = *(const float4*)&xr[(lane + 32*i)*4];
        sum += v[i].x + v[i].y + v[i].z + v[i].w;
    }
    #pragma unroll
    for (int off = 16; off > 0; off >>= 1)
        sum += __shfl_xor_sync(0xffffffffu, sum, off);
    float mu = sum * (1.f/768.f);

    float sq = 0.f;
    #pragma unroll
    for (int i = 0; i < 6; i++) {
        v[i].x -= mu; v[i].y -= mu; v[i].z -= mu; v[i].w -= mu;
        sq += v[i].x*v[i].x + v[i].y*v[i].y + v[i].z*v[i].z + v[i].w*v[i].w;
    }
    #pragma unroll
    for (int off = 16; off > 0; off >>= 1)
        sq += __shfl_xor_sync(0xffffffffu, sq, off);
    float rstd = rsqrtf(sq*(1.f/768.f) + 1e-5f);

    #pragma unroll
    for (int i = 0; i < 6; i++) {
        int e = (lane + 32*i)*4;
        float4 sv = *(const float4*)&s[e];
        float4 bv = *(const float4*)&b[e];
        float y0 = v[i].x*rstd*sv.x + bv.x;
        float y1 = v[i].y*rstd*sv.y + bv.y;
        float y2 = v[i].z*rstd*sv.z + bv.z;
        float y3 = v[i].w*rstd*sv.w + bv.w;
        *(uint2*)&ho[(size_t)row*384 + (lane + 32*i)*2] =
            make_uint2(packh2(y0, y1), packh2(y2, y3));
    }
}

// ---------------- unpatchify ----------------
__global__ void __launch_bounds__(256) out_kernel(const float* __restrict__ x,
                                                  const float* __restrict__ W_out,
                                                  float* __restrict__ out)
{
    __shared__ float srow[8*768];
    const int tid = threadIdx.x, lane = tid & 31, wid = tid >> 5;
    const int rowbase = blockIdx.x*8;

    #pragma unroll
    for (int i = 0; i < 6; i++) {
        int f = tid + i*256;
        int r = f / 192, pos = f % 192;
        *(float4*)&srow[r*768 + pos*4] =
            *(const float4*)&x[(size_t)(rowbase+r)*DIM + pos*4];
    }
    __syncthreads();

    const int row = rowbase + wid;
    const int v  = lane >> 4;
    const int pq = lane & 15;
    const float* xrow = &srow[wid*768];
    const float* wcol = W_out + (size_t)v*DIM*16 + pq;

    float acc = 0.f;
    #pragma unroll 8
    for (int d = 0; d < DIM; d++)
        acc = fmaf(xrow[d], wcol[(size_t)d*16], acc);

    int bb = row >> 10;
    int e  = (row >> 9) & 1;
    int n  = row & 511;
    int h  = n >> 5, w = n & 31;
    int p  = pq >> 2, q = pq & 3;
    size_t oidx = (size_t)bb*32768 + (size_t)v*16384
                + (size_t)(h*4+p)*256 + (w*4+q)*2 + e;
    out[oidx] = acc;
}

// ---------------- driver ----------------
extern "C" void kernel_launch(void* const* d_in, const int* in_sizes, int n_in,
                              void* d_out, int out_size)
{
    const float* fields   = (const float*)d_in[0];
    const unsigned char* visible = (const unsigned char*)d_in[1];
    const float* z        = (const float*)d_in[2];
    const float* W_in     = (const float*)d_in[3];
    const float* W_out    = (const float*)d_in[4];
    const float* noise_W  = (const float*)d_in[5];
    const float* noise_b  = (const float*)d_in[6];
    const float* mask_emb = (const float*)d_in[7];
    const float* pos_emb  = (const float*)d_in[8];
    const float* ln1_s    = (const float*)d_in[9];
    const float* ln1_b    = (const float*)d_in[10];
    const float* Wqkv     = (const float*)d_in[11];
    const float* bqkv     = (const float*)d_in[12];
    const float* Wo       = (const float*)d_in[13];
    const float* bo       = (const float*)d_in[14];
    const float* ln2_s    = (const float*)d_in[15];
    const float* ln2_b    = (const float*)d_in[16];
    const float* W1       = (const float*)d_in[17];
    const float* b1       = (const float*)d_in[18];
    const float* W2       = (const float*)d_in[19];
    const float* b2       = (const float*)d_in[20];

    float *xp;
    unsigned *qkvpp, *ap, *mp, *zp;
    unsigned *wq, *wo, *w1, *w2, *nw;
    cudaGetSymbolAddress((void**)&xp,    g_x);
    cudaGetSymbolAddress((void**)&qkvpp, g_qkvp);
    cudaGetSymbolAddress((void**)&ap,    g_a);
    cudaGetSymbolAddress((void**)&mp,    g_m);
    cudaGetSymbolAddress((void**)&zp,    g_z2);
    cudaGetSymbolAddress((void**)&wq,    g_wqkv);
    cudaGetSymbolAddress((void**)&wo,    g_wo);
    cudaGetSymbolAddress((void**)&w1,    g_w1);
    cudaGetSymbolAddress((void**)&w2,    g_w2);
    cudaGetSymbolAddress((void**)&nw,    g_nw);

    cudaFuncSetAttribute(gemm_h, cudaFuncAttributeMaxDynamicSharedMemorySize, GH_SMEM);

    probe_visible<<<1, 32>>>(visible);

    {
        long t4;
        t4 = (long)LAYERS*384*QKVD/4;
        round_W4<<<(unsigned)((t4+255)/256), 256>>>(Wqkv, wq, QKVD, t4);
        t4 = (long)LAYERS*384*DIM/4;
        round_W4<<<(unsigned)((t4+255)/256), 256>>>(Wo, wo, DIM, t4);
        t4 = (long)LAYERS*384*DMLP/4;
        round_W4<<<(unsigned)((t4+255)/256), 256>>>(W1, w1, DMLP, t4);
        t4 = (long)LAYERS*1536*DIM/4;
        round_W4<<<(unsigned)((t4+255)/256), 256>>>(W2, w2, DIM, t4);
        t4 = (long)384*DIM/4;
        round_W4<<<(unsigned)((t4+255)/256), 256>>>(noise_W, nw, DIM, t4);
        t4 = (long)ROWS*384/4;
        round_A4<<<(unsigned)((t4+255)/256), 256>>>(z, zp, t4);
    }

    embed_kernel<<<ROWS, 256>>>(fields, visible, W_in, mask_emb, pos_emb, noise_b, xp);

    // x += z @ noise_W
    gemm_h<<<dim3(DIM/128, ROWS/128), 256, GH_SMEM>>>(
        zp, 384, nw, DIM, xp, nullptr, DIM, DIM, nullptr, 2);

    for (int l = 0; l < LAYERS; l++) {
        ln_h<<<ROWS/8, 256>>>(xp, ln1_s + l*DIM, ln1_b + l*DIM, ap);

        gemm_h<<<dim3(QKVD/128, ROWS/128), 256, GH_SMEM>>>(
            ap, 384,
            wq + (size_t)l*384*QKVD, QKVD,
            nullptr, qkvpp, QKVD, DIM, bqkv + (size_t)l*QKVD, 4);

        attn_flash<<<dim3(NTOK/128, BE*NHEADS), 256>>>(qkvpp, ap);

        gemm_h<<<dim3(DIM/128, ROWS/128), 256, GH_SMEM>>>(
            ap, 384,
            wo + (size_t)l*384*DIM, DIM,
            xp, nullptr, DIM, DIM, bo + (size_t)l*DIM, 2);

        ln_h<<<ROWS/8, 256>>>(xp, ln2_s + l*DIM, ln2_b + l*DIM, ap);

        gemm_h<<<dim3(DMLP/128, ROWS/128), 256, GH_SMEM>>>(
            ap, 384,
            w1 + (size_t)l*384*DMLP, DMLP,
            nullptr, mp, DMLP, DIM, b1 + (size_t)l*DMLP, 1|4);

        gemm_h<<<dim3(DIM/128, ROWS/128), 256, GH_SMEM>>>(
            mp, 1536,
            w2 + (size_t)l*1536*DIM, DIM,
            xp, nullptr, DIM, DMLP, b2 + (size_t)l*DIM, 2);
    }

    out_kernel<<<ROWS/8, 256>>>(xp, W_out, (float*)d_out);
}

// round 17
// speedup vs baseline: 1.1838x; 1.1196x over previous
#include <cuda_runtime.h>
#include <cuda_fp16.h>
#include <cstddef>

// ---------------- problem constants ----------------
#define BATCH   8
#define EMEM    2
#define BE      16
#define NTOK    512
#define ROWS    (BE*NTOK)   // 8192
#define DIM     768
#define NHEADS  12
#define HDIM    64
#define LAYERS  8
#define DMLP    3072
#define QKVD    2304
#define VIEWS   2

// ---------------- scratch ----------------
__device__ float g_x[ROWS*DIM];
__device__ int   g_vismode;
__device__ unsigned g_qkvp[ROWS*(QKVD/2)];
__device__ unsigned g_a[ROWS*(DIM/2)];
__device__ unsigned g_m[ROWS*(DMLP/2)];
__device__ unsigned g_z2[ROWS*(DIM/2)];
__device__ unsigned g_wqkv[LAYERS*(DIM/2)*QKVD];
__device__ unsigned g_wo  [LAYERS*(DIM/2)*DIM];
__device__ unsigned g_w1  [LAYERS*(DIM/2)*DMLP];
__device__ unsigned g_w2  [LAYERS*(DMLP/2)*DIM];
__device__ unsigned g_nw  [(DIM/2)*DIM];

// ---------------- helpers ----------------
__device__ __forceinline__ float gelu_f(float x) {
    float x3 = x*x*x;
    return 0.5f*x*(1.f + tanhf(0.79788456080286535588f*(x + 0.044715f*x3)));
}

__device__ __forceinline__ unsigned packh2(float x, float y) {
    __half2 h = __floats2half2_rn(x, y);
    return *reinterpret_cast<unsigned*>(&h);
}

__device__ __forceinline__ void mma_f16(float& c0, float& c1, float& c2, float& c3,
                                        unsigned a0, unsigned a1, unsigned a2, unsigned a3,
                                        unsigned b0, unsigned b1)
{
    asm volatile(
        "mma.sync.aligned.m16n8k16.row.col.f32.f16.f16.f32 "
        "{%0,%1,%2,%3},{%4,%5,%6,%7},{%8,%9},{%0,%1,%2,%3};"
        : "+f"(c0), "+f"(c1), "+f"(c2), "+f"(c3)
        : "r"(a0), "r"(a1), "r"(a2), "r"(a3), "r"(b0), "r"(b1));
}

// ---------------- probe dtype of `visible` ----------------
__global__ void probe_visible(const unsigned char* __restrict__ vis) {
    if (threadIdx.x == 0 && blockIdx.x == 0) {
        int nz1 = 0, nz3f = 0;
        for (int i = 0; i < 4096; i++) {
            int m = i & 3;
            if (m == 1 && vis[i]) nz1++;
            if (m == 3 && vis[i]) nz3f++;
        }
        if (nz1 != 0)       g_vismode = 0;
        else if (nz3f != 0) g_vismode = 2;
        else                g_vismode = 1;
    }
}

// ---------------- weight/activation rounding (vectorized) ----------------
__global__ void round_W4(const float* __restrict__ W, unsigned* __restrict__ o,
                         int N, long total4)
{
    long i4 = (long)blockIdx.x*256 + threadIdx.x;
    if (i4 >= total4) return;
    int n4 = N >> 2;
    long kp = i4 / n4;
    int nq = (int)(i4 % n4) * 4;
    float4 a = *(const float4*)&W[(size_t)(2*kp)*N + nq];
    float4 b = *(const float4*)&W[(size_t)(2*kp+1)*N + nq];
    uint4 r;
    r.x = packh2(a.x, b.x);
    r.y = packh2(a.y, b.y);
    r.z = packh2(a.z, b.z);
    r.w = packh2(a.w, b.w);
    *(uint4*)&o[kp*N + nq] = r;
}

__global__ void round_A4(const float* __restrict__ X, unsigned* __restrict__ o, long total4)
{
    long i4 = (long)blockIdx.x*256 + threadIdx.x;
    if (i4 >= total4) return;
    float4 v0 = *(const float4*)&X[8*i4];
    float4 v1 = *(const float4*)&X[8*i4 + 4];
    uint4 r;
    r.x = packh2(v0.x, v0.y);
    r.y = packh2(v0.z, v0.w);
    r.z = packh2(v1.x, v1.y);
    r.w = packh2(v1.z, v1.w);
    *(uint4*)&o[4*i4] = r;
}

// ---------------- patch embed + mask + pos + noise bias ----------------
__global__ void embed_kernel(const float* __restrict__ fields,
                             const unsigned char* __restrict__ visible,
                             const float* __restrict__ W_in,
                             const float* __restrict__ mask_emb,
                             const float* __restrict__ pos_emb,
                             const float* __restrict__ noise_b,
                             float* __restrict__ xout)
{
    int row = blockIdx.x;
    int be  = row >> 9;
    int n   = row & 511;
    int b   = be >> 1;
    int h   = n >> 5;
    int w   = n & 31;

    int vi = b*NTOK + n;
    bool vis;
    int mode = g_vismode;
    if (mode == 1)      vis = ((const int*)visible)[vi] != 0;
    else if (mode == 2) vis = ((const float*)visible)[vi] != 0.f;
    else                vis = visible[vi] != 0;

    __shared__ float fv[32];
    if (threadIdx.x < 32) {
        int v = threadIdx.x >> 4;
        int p = (threadIdx.x >> 2) & 3;
        int q = threadIdx.x & 3;
        fv[threadIdx.x] = fields[((size_t)(b*VIEWS + v)*64 + (h*4+p))*128 + (w*4+q)];
    }
    __syncthreads();

    for (int d = threadIdx.x; d < DIM; d += blockDim.x) {
        float acc;
        if (vis) {
            acc = 0.f;
            #pragma unroll
            for (int t = 0; t < 32; t++) acc += fv[t] * W_in[t*DIM + d];
        } else {
            acc = mask_emb[d];
        }
        xout[(size_t)row*DIM + d] = acc + pos_emb[n*DIM + d] + noise_b[d];
    }
}

// ---------------- fp16 GEMM: 128x128 tiles, k32, 4-stage cp.async (hoisted issue) ----------------
// flags: bit0 gelu, bit1 accumulate fp32, bit2 write fp16-pair output
#define GH_SMEM ((4*128*20 + 4*16*136)*4)   // 75776 B
__global__ void __launch_bounds__(256) gemm_h(
    const unsigned* __restrict__ Apk, int ldap,
    const unsigned* __restrict__ Wp, int ldb,
    float* __restrict__ Cf, unsigned* __restrict__ Cp, int ldc,
    int K, const float* __restrict__ bias, int flags)
{
    extern __shared__ unsigned sm[];
    unsigned* As = sm;                 // [4][128][20]
    unsigned* Bs = As + 4*128*20;      // [4][16][136]

    const int tid = threadIdx.x, lane = tid & 31, wid = tid >> 5;
    const int warpM = (wid >> 2)*64, warpN = (wid & 3)*32;
    const int gid = lane >> 2, tig = lane & 3;
    const int row0 = blockIdx.y*128, col0 = blockIdx.x*128;
    const int kt32 = K >> 5;

    float acc[4][4][4] = {};

    auto issue = [&](int kt) {
        int st = kt & 3;
        int kp0 = kt << 4;
        #pragma unroll
        for (int i = 0; i < 2; i++) {
            int c = tid + i*256;
            int r = c >> 2, q = (c & 3)*4;
            const unsigned* s = &Apk[(size_t)(row0+r)*ldap + kp0 + q];
            unsigned d = (unsigned)__cvta_generic_to_shared(&As[st*2560 + r*20 + q]);
            asm volatile("cp.async.cg.shared.global [%0],[%1],16;"::"r"(d),"l"(s));
            int kp = c >> 5, nq = (c & 31)*4;
            const unsigned* s1 = &Wp[(size_t)(kp0+kp)*ldb + col0 + nq];
            unsigned d1 = (unsigned)__cvta_generic_to_shared(&Bs[st*2176 + kp*136 + nq]);
            asm volatile("cp.async.cg.shared.global [%0],[%1],16;"::"r"(d1),"l"(s1));
        }
        asm volatile("cp.async.commit_group;");
    };

    issue(0); issue(1);

    for (int kt = 0; kt < kt32; kt++) {
        int st = kt & 3;
        // hoisted issue: slot (kt+2)&3 belongs to tile kt-2, consumed 2 barriers ago -> safe
        if (kt + 2 < kt32) issue(kt + 2);
        else asm volatile("cp.async.commit_group;");
        asm volatile("cp.async.wait_group 2;");
        __syncthreads();

        #pragma unroll
        for (int t = 0; t < 2; t++) {
            unsigned a[4][4];
            #pragma unroll
            for (int mi = 0; mi < 4; mi++) {
                int base = st*2560 + (warpM + mi*16 + gid)*20 + t*8;
                a[mi][0] = As[base + tig];
                a[mi][1] = As[base + 160 + tig];
                a[mi][2] = As[base + tig + 4];
                a[mi][3] = As[base + 160 + tig + 4];
            }
            #pragma unroll
            for (int ni = 0; ni < 4; ni++) {
                int cb = warpN + ni*8 + gid;
                unsigned b0 = Bs[st*2176 + (t*8+tig  )*136 + cb];
                unsigned b1 = Bs[st*2176 + (t*8+tig+4)*136 + cb];
                #pragma unroll
                for (int mi = 0; mi < 4; mi++) {
                    mma_f16(acc[mi][ni][0], acc[mi][ni][1], acc[mi][ni][2], acc[mi][ni][3],
                            a[mi][0], a[mi][1], a[mi][2], a[mi][3], b0, b1);
                }
            }
        }
    }

    #pragma unroll
    for (int mi = 0; mi < 4; mi++) {
        #pragma unroll
        for (int ni = 0; ni < 4; ni++) {
            int col = col0 + warpN + ni*8 + tig*2;
            float bia0 = bias ? bias[col]   : 0.f;
            float bia1 = bias ? bias[col+1] : 0.f;
            #pragma unroll
            for (int half = 0; half < 2; half++) {
                int row = row0 + warpM + mi*16 + gid + half*8;
                float v0 = acc[mi][ni][half*2 + 0] + bia0;
                float v1 = acc[mi][ni][half*2 + 1] + bia1;
                if (flags & 1) { v0 = gelu_f(v0); v1 = gelu_f(v1); }
                if (flags & 4) {
                    Cp[(size_t)row*(ldc >> 1) + (col >> 1)] = packh2(v0, v1);
                } else {
                    size_t ci = (size_t)row*ldc + col;
                    if (flags & 2) { v0 += Cf[ci]; v1 += Cf[ci+1]; }
                    Cf[ci]   = v0;
                    Cf[ci+1] = v1;
                }
            }
        }
    }
}

// ---------------- flash attention: single pass, register S, online softmax ----------------
__global__ void __launch_bounds__(256, 2) attn_flash(const unsigned* __restrict__ qkvp,
                                                     unsigned* __restrict__ Ha)
{
    __shared__ unsigned Kb[2][64*36];
    __shared__ unsigned Vr[2][64*36];
    __shared__ unsigned Vp[32*72];

    const int bh = blockIdx.y;
    const int qt = blockIdx.x * 128;
    const int be = bh / NHEADS, nh = bh % NHEADS;
    const unsigned* Qg = qkvp + (size_t)be*NTOK*1152 + nh*32;
    const unsigned* Kg = Qg + 384;
    const unsigned* Vg = Qg + 768;

    const int tid = threadIdx.x, lane = tid & 31, wid = tid >> 5;
    const int gid = lane >> 2, tig = lane & 3;

    auto pref = [&](int kt) {
        int buf = kt & 1;
        #pragma unroll
        for (int i = 0; i < 2; i++) {
            int c = tid + i*256;
            int r = c >> 3, q = (c & 7)*4;
            unsigned dk = (unsigned)__cvta_generic_to_shared(&Kb[buf][r*36 + q]);
            const unsigned* sk = &Kg[(size_t)(kt*64+r)*1152 + q];
            asm volatile("cp.async.cg.shared.global [%0],[%1],16;"::"r"(dk),"l"(sk));
            unsigned dv = (unsigned)__cvta_generic_to_shared(&Vr[buf][r*36 + q]);
            const unsigned* sv = &Vg[(size_t)(kt*64+r)*1152 + q];
            asm volatile("cp.async.cg.shared.global [%0],[%1],16;"::"r"(dv),"l"(sv));
        }
        asm volatile("cp.async.commit_group;");
    };

    pref(0); pref(1);

    unsigned qf[4][4];
    {
        const unsigned* Qrow = &Qg[(size_t)(qt + wid*16)*1152];
        __half2 s8 = __half2half2(__float2half(0.125f));
        #pragma unroll
        for (int t = 0; t < 4; t++) {
            qf[t][0] = Qrow[(size_t)(gid  )*1152 + t*8 + tig];
            qf[t][1] = Qrow[(size_t)(gid+8)*1152 + t*8 + tig];
            qf[t][2] = Qrow[(size_t)(gid  )*1152 + t*8 + tig+4];
            qf[t][3] = Qrow[(size_t)(gid+8)*1152 + t*8 + tig+4];
            #pragma unroll
            for (int j = 0; j < 4; j++) {
                __half2 h = __hmul2(*reinterpret_cast<__half2*>(&qf[t][j]), s8);
                qf[t][j] = *reinterpret_cast<unsigned*>(&h);
            }
        }
    }

    float m0 = -1e30f, m1 = -1e30f, l0 = 0.f, l1 = 0.f;
    float acc[8][4] = {};

    for (int kt = 0; kt < 8; kt++) {
        const int buf = kt & 1;
        asm volatile("cp.async.wait_group 1;");
        __syncthreads();

        float s[8][4] = {};
        #pragma unroll
        for (int t = 0; t < 4; t++) {
            #pragma unroll
            for (int ni = 0; ni < 8; ni++) {
                int cb = ni*8 + gid;
                unsigned b0 = Kb[buf][cb*36 + t*8 + tig];
                unsigned b1 = Kb[buf][cb*36 + t*8 + tig+4];
                mma_f16(s[ni][0], s[ni][1], s[ni][2], s[ni][3],
                        qf[t][0], qf[t][1], qf[t][2], qf[t][3], b0, b1);
            }
        }

        float tm0 = -1e30f, tm1 = -1e30f;
        #pragma unroll
        for (int ni = 0; ni < 8; ni++) {
            tm0 = fmaxf(tm0, fmaxf(s[ni][0], s[ni][1]));
            tm1 = fmaxf(tm1, fmaxf(s[ni][2], s[ni][3]));
        }
        tm0 = fmaxf(tm0, __shfl_xor_sync(0xffffffffu, tm0, 1));
        tm0 = fmaxf(tm0, __shfl_xor_sync(0xffffffffu, tm0, 2));
        tm1 = fmaxf(tm1, __shfl_xor_sync(0xffffffffu, tm1, 1));
        tm1 = fmaxf(tm1, __shfl_xor_sync(0xffffffffu, tm1, 2));
        float nm0 = fmaxf(m0, tm0), nm1 = fmaxf(m1, tm1);
        float f0 = __expf(m0 - nm0), f1 = __expf(m1 - nm1);
        m0 = nm0; m1 = nm1;

        unsigned pp[8][2];
        float ts0 = 0.f, ts1 = 0.f;
        #pragma unroll
        for (int ni = 0; ni < 8; ni++) {
            float p0 = __expf(s[ni][0] - m0), p1 = __expf(s[ni][1] - m0);
            float p2 = __expf(s[ni][2] - m1), p3 = __expf(s[ni][3] - m1);
            ts0 += p0 + p1; ts1 += p2 + p3;
            pp[ni][0] = packh2(p0, p1);
            pp[ni][1] = packh2(p2, p3);
        }
        ts0 += __shfl_xor_sync(0xffffffffu, ts0, 1);
        ts0 += __shfl_xor_sync(0xffffffffu, ts0, 2);
        ts1 += __shfl_xor_sync(0xffffffffu, ts1, 1);
        ts1 += __shfl_xor_sync(0xffffffffu, ts1, 2);
        l0 = l0*f0 + ts0;
        l1 = l1*f1 + ts1;
        #pragma unroll
        for (int ni = 0; ni < 8; ni++) {
            acc[ni][0] *= f0; acc[ni][1] *= f0;
            acc[ni][2] *= f1; acc[ni][3] *= f1;
        }

        {
            int kp = tid >> 3, dpb = tid & 7;
            #pragma unroll
            for (int i = 0; i < 4; i++) {
                int dp = dpb + 8*i;
                unsigned r0 = Vr[buf][(2*kp  )*36 + dp];
                unsigned r1 = Vr[buf][(2*kp+1)*36 + dp];
                Vp[kp*72 + 2*dp    ] = __byte_perm(r0, r1, 0x5410);
                Vp[kp*72 + 2*dp + 1] = __byte_perm(r0, r1, 0x7632);
            }
        }
        __syncthreads();
        if (kt + 2 < 8) pref(kt + 2);
        else asm volatile("cp.async.commit_group;");

        #pragma unroll
        for (int b = 0; b < 4; b++) {
            unsigned a0 = pp[2*b  ][0], a1 = pp[2*b  ][1];
            unsigned a2 = pp[2*b+1][0], a3 = pp[2*b+1][1];
            #pragma unroll
            for (int ni = 0; ni < 8; ni++) {
                int cb = ni*8 + gid;
                unsigned b0 = Vp[(b*8 + tig  )*72 + cb];
                unsigned b1 = Vp[(b*8 + tig+4)*72 + cb];
                mma_f16(acc[ni][0], acc[ni][1], acc[ni][2], acc[ni][3],
                        a0, a1, a2, a3, b0, b1);
            }
        }
    }

    float il0 = 1.f / l0, il1 = 1.f / l1;
    int row0 = be*NTOK + qt + wid*16 + gid;
    #pragma unroll
    for (int ni = 0; ni < 8; ni++) {
        int colp = nh*32 + ni*4 + tig;
        Ha[(size_t)row0*384 + colp]     = packh2(acc[ni][0]*il0, acc[ni][1]*il0);
        Ha[(size_t)(row0+8)*384 + colp] = packh2(acc[ni][2]*il1, acc[ni][3]*il1);
    }
}

// ---------------- layernorm: warp per row ----------------
__global__ void __launch_bounds__(256) ln_h(const float* __restrict__ x,
                                            const float* __restrict__ s,
                                            const float* __restrict__ b,
                                            unsigned* __restrict__ ho)
{
    const int lane = threadIdx.x & 31, wid = threadIdx.x >> 5;
    const int row = blockIdx.x*8 + wid;
    const float* xr = x + (size_t)row*DIM;

    float4 v[6];
    float sum = 0.f;
    #pragma unroll
    for (int i = 0; i < 6; i++) {
        v[i] = *(const float4*)&xr[(lane + 32*i)*4];
        sum += v[i].x + v[i].y + v[i].z + v[i].w;
    }
    #pragma unroll
    for (int off = 16; off > 0; off >>= 1)
        sum += __shfl_xor_sync(0xffffffffu, sum, off);
    float mu = sum * (1.f/768.f);

    float sq = 0.f;
    #pragma unroll
    for (int i = 0; i < 6; i++) {
        v[i].x -= mu; v[i].y -= mu; v[i].z -= mu; v[i].w -= mu;
        sq += v[i].x*v[i].x + v[i].y*v[i].y + v[i].z*v[i].z + v[i].w*v[i].w;
    }
    #pragma unroll
    for (int off = 16; off > 0; off >>= 1)
        sq += __shfl_xor_sync(0xffffffffu, sq, off);
    float rstd = rsqrtf(sq*(1.f/768.f) + 1e-5f);

    #pragma unroll
    for (int i = 0; i < 6; i++) {
        int e = (lane + 32*i)*4;
        float4 sv = *(const float4*)&s[e];
        float4 bv = *(const float4*)&b[e];
        float y0 = v[i].x*rstd*sv.x + bv.x;
        float y1 = v[i].y*rstd*sv.y + bv.y;
        float y2 = v[i].z*rstd*sv.z + bv.z;
        float y3 = v[i].w*rstd*sv.w + bv.w;
        *(uint2*)&ho[(size_t)row*384 + (lane + 32*i)*2] =
            make_uint2(packh2(y0, y1), packh2(y2, y3));
    }
}

// ---------------- unpatchify ----------------
__global__ void __launch_bounds__(256) out_kernel(const float* __restrict__ x,
                                                  const float* __restrict__ W_out,
                                                  float* __restrict__ out)
{
    __shared__ float srow[8*768];
    const int tid = threadIdx.x, lane = tid & 31, wid = tid >> 5;
    const int rowbase = blockIdx.x*8;

    #pragma unroll
    for (int i = 0; i < 6; i++) {
        int f = tid + i*256;
        int r = f / 192, pos = f % 192;
        *(float4*)&srow[r*768 + pos*4] =
            *(const float4*)&x[(size_t)(rowbase+r)*DIM + pos*4];
    }
    __syncthreads();

    const int row = rowbase + wid;
    const int v  = lane >> 4;
    const int pq = lane & 15;
    const float* xrow = &srow[wid*768];
    const float* wcol = W_out + (size_t)v*DIM*16 + pq;

    float acc = 0.f;
    #pragma unroll 8
    for (int d = 0; d < DIM; d++)
        acc = fmaf(xrow[d], wcol[(size_t)d*16], acc);

    int bb = row >> 10;
    int e  = (row >> 9) & 1;
    int n  = row & 511;
    int h  = n >> 5, w = n & 31;
    int p  = pq >> 2, q = pq & 3;
    size_t oidx = (size_t)bb*32768 + (size_t)v*16384
                + (size_t)(h*4+p)*256 + (w*4+q)*2 + e;
    out[oidx] = acc;
}

// ---------------- driver ----------------
extern "C" void kernel_launch(void* const* d_in, const int* in_sizes, int n_in,
                              void* d_out, int out_size)
{
    const float* fields   = (const float*)d_in[0];
    const unsigned char* visible = (const unsigned char*)d_in[1];
    const float* z        = (const float*)d_in[2];
    const float* W_in     = (const float*)d_in[3];
    const float* W_out    = (const float*)d_in[4];
    const float* noise_W  = (const float*)d_in[5];
    const float* noise_b  = (const float*)d_in[6];
    const float* mask_emb = (const float*)d_in[7];
    const float* pos_emb  = (const float*)d_in[8];
    const float* ln1_s    = (const float*)d_in[9];
    const float* ln1_b    = (const float*)d_in[10];
    const float* Wqkv     = (const float*)d_in[11];
    const float* bqkv     = (const float*)d_in[12];
    const float* Wo       = (const float*)d_in[13];
    const float* bo       = (const float*)d_in[14];
    const float* ln2_s    = (const float*)d_in[15];
    const float* ln2_b    = (const float*)d_in[16];
    const float* W1       = (const float*)d_in[17];
    const float* b1       = (const float*)d_in[18];
    const float* W2       = (const float*)d_in[19];
    const float* b2       = (const float*)d_in[20];

    float *xp;
    unsigned *qkvpp, *ap, *mp, *zp;
    unsigned *wq, *wo, *w1, *w2, *nw;
    cudaGetSymbolAddress((void**)&xp,    g_x);
    cudaGetSymbolAddress((void**)&qkvpp, g_qkvp);
    cudaGetSymbolAddress((void**)&ap,    g_a);
    cudaGetSymbolAddress((void**)&mp,    g_m);
    cudaGetSymbolAddress((void**)&zp,    g_z2);
    cudaGetSymbolAddress((void**)&wq,    g_wqkv);
    cudaGetSymbolAddress((void**)&wo,    g_wo);
    cudaGetSymbolAddress((void**)&w1,    g_w1);
    cudaGetSymbolAddress((void**)&w2,    g_w2);
    cudaGetSymbolAddress((void**)&nw,    g_nw);

    cudaFuncSetAttribute(gemm_h, cudaFuncAttributeMaxDynamicSharedMemorySize, GH_SMEM);

    probe_visible<<<1, 32>>>(visible);

    {
        long t4;
        t4 = (long)LAYERS*384*QKVD/4;
        round_W4<<<(unsigned)((t4+255)/256), 256>>>(Wqkv, wq, QKVD, t4);
        t4 = (long)LAYERS*384*DIM/4;
        round_W4<<<(unsigned)((t4+255)/256), 256>>>(Wo, wo, DIM, t4);
        t4 = (long)LAYERS*384*DMLP/4;
        round_W4<<<(unsigned)((t4+255)/256), 256>>>(W1, w1, DMLP, t4);
        t4 = (long)LAYERS*1536*DIM/4;
        round_W4<<<(unsigned)((t4+255)/256), 256>>>(W2, w2, DIM, t4);
        t4 = (long)384*DIM/4;
        round_W4<<<(unsigned)((t4+255)/256), 256>>>(noise_W, nw, DIM, t4);
        t4 = (long)ROWS*384/4;
        round_A4<<<(unsigned)((t4+255)/256), 256>>>(z, zp, t4);
    }

    embed_kernel<<<ROWS, 256>>>(fields, visible, W_in, mask_emb, pos_emb, noise_b, xp);

    // x += z @ noise_W
    gemm_h<<<dim3(DIM/128, ROWS/128), 256, GH_SMEM>>>(
        zp, 384, nw, DIM, xp, nullptr, DIM, DIM, nullptr, 2);

    for (int l = 0; l < LAYERS; l++) {
        ln_h<<<ROWS/8, 256>>>(xp, ln1_s + l*DIM, ln1_b + l*DIM, ap);

        gemm_h<<<dim3(QKVD/128, ROWS/128), 256, GH_SMEM>>>(
            ap, 384,
            wq + (size_t)l*384*QKVD, QKVD,
            nullptr, qkvpp, QKVD, DIM, bqkv + (size_t)l*QKVD, 4);

        attn_flash<<<dim3(NTOK/128, BE*NHEADS), 256>>>(qkvpp, ap);

        gemm_h<<<dim3(DIM/128, ROWS/128), 256, GH_SMEM>>>(
            ap, 384,
            wo + (size_t)l*384*DIM, DIM,
            xp, nullptr, DIM, DIM, bo + (size_t)l*DIM, 2);

        ln_h<<<ROWS/8, 256>>>(xp, ln2_s + l*DIM, ln2_b + l*DIM, ap);

        gemm_h<<<dim3(DMLP/128, ROWS/128), 256, GH_SMEM>>>(
            ap, 384,
            w1 + (size_t)l*384*DMLP, DMLP,
            nullptr, mp, DMLP, DIM, b1 + (size_t)l*DMLP, 1|4);

        gemm_h<<<dim3(DIM/128, ROWS/128), 256, GH_SMEM>>>(
            mp, 1536,
            w2 + (size_t)l*1536*DIM, DIM,
            xp, nullptr, DIM, DMLP, b2 + (size_t)l*DIM, 2);
    }

    out_kernel<<<ROWS/8, 256>>>(xp, W_out, (float*)d_out);
}